// round 16
// baseline (speedup 1.0000x reference)
#include <cuda_runtime.h>
#include <math.h>
#include <float.h>

#define N_NODES 50000
#define N_EDGES 800000
#define DD      128
#define AA      4
#define HH      2
#define GG      128
#define NEG     0.2f

// ---------------- device scratch (static, no allocations) ----------------
__device__ float g_xh[N_NODES * HH * DD];    // per-head node features [N,2,128] (51.2MB)
__device__ float g_acc[N_NODES * DD];        // head-mean accumulator / layer output (25.6MB)
__device__ float g_ebuf[N_EDGES * AA];       // edge features between layers (12.8MB)
__device__ float g_alpha[N_EDGES * HH];      // raw alpha, then exp(alpha-max) (6.4MB)
__device__ float g_ai[N_NODES * HH];
__device__ float g_aj[N_NODES * HH];
__device__ float g_amax[N_NODES * HH];
__device__ float g_den[N_NODES * HH];

// ---------------- helpers ----------------
__device__ __forceinline__ void atomicMaxFloat(float* addr, float value) {
    // works across mixed signs: int ordering matches float for >=0,
    // reversed-unsigned ordering matches for <0; atomics serialize.
    if (value >= 0.0f)
        atomicMax((int*)addr, __float_as_int(value));
    else
        atomicMin((unsigned int*)addr, __float_as_uint(value));
}

// ---------------- 1) node GEMM: xh = in @ linN + bias --------------------
// block = 128 threads, computes 16 rows x 256 cols (2 cols/thread).
// layer==0 reads xin; otherwise reads relu(g_acc).
__global__ void gemm_node(const float* __restrict__ xin,
                          const float* __restrict__ W,
                          const float* __restrict__ bias,
                          int layer) {
    __shared__ float sIn[16][DD];
    const int row0 = blockIdx.x * 16;
    const int t = threadIdx.x;

    const float* in = (layer == 0) ? xin : g_acc;
    for (int i = t; i < 16 * DD; i += 128) {
        int m = i >> 7, k = i & 127;
        float v = in[(size_t)(row0 + m) * DD + k];
        if (layer != 0) v = fmaxf(v, 0.0f);
        sIn[m][k] = v;
    }
    __syncthreads();

    float acc0[16], acc1[16];
#pragma unroll
    for (int m = 0; m < 16; m++) { acc0[m] = 0.0f; acc1[m] = 0.0f; }

    const int c0 = 2 * t;
#pragma unroll 4
    for (int k = 0; k < DD; k++) {
        float2 w = *reinterpret_cast<const float2*>(&W[k * 256 + c0]);
#pragma unroll
        for (int m = 0; m < 16; m++) {
            float xv = sIn[m][k];
            acc0[m] = fmaf(xv, w.x, acc0[m]);
            acc1[m] = fmaf(xv, w.y, acc1[m]);
        }
    }

    float b0 = bias[c0], b1 = bias[c0 + 1];
#pragma unroll
    for (int m = 0; m < 16; m++) {
        size_t o = (size_t)(row0 + m) * 256 + c0;
        g_xh[o]     = acc0[m] + b0;
        g_xh[o + 1] = acc1[m] + b1;
    }
}

// ---------------- 2) per-node prep: ai/aj dots, acc init, amax/den init ---
// one block (128 threads) per node
__global__ void node_prep(const float* __restrict__ att) {
    const int n = blockIdx.x;
    const int d = threadIdx.x;

    float x0 = g_xh[(size_t)n * 256 + d];
    float x1 = g_xh[(size_t)n * 256 + 128 + d];
    g_acc[(size_t)n * DD + d] = 0.5f * (x0 + x1);

    float ai0 = x0 * att[d];
    float aj0 = x0 * att[128 + d];
    float ai1 = x1 * att[260 + d];
    float aj1 = x1 * att[260 + 128 + d];

#pragma unroll
    for (int o = 16; o > 0; o >>= 1) {
        ai0 += __shfl_down_sync(0xFFFFFFFFu, ai0, o);
        aj0 += __shfl_down_sync(0xFFFFFFFFu, aj0, o);
        ai1 += __shfl_down_sync(0xFFFFFFFFu, ai1, o);
        aj1 += __shfl_down_sync(0xFFFFFFFFu, aj1, o);
    }
    __shared__ float s[4][4];
    int w = d >> 5, l = d & 31;
    if (l == 0) { s[w][0] = ai0; s[w][1] = aj0; s[w][2] = ai1; s[w][3] = aj1; }
    __syncthreads();
    if (d == 0) {
        float vai0 = s[0][0] + s[1][0] + s[2][0] + s[3][0];
        float vaj0 = s[0][1] + s[1][1] + s[2][1] + s[3][1];
        float vai1 = s[0][2] + s[1][2] + s[2][2] + s[3][2];
        float vaj1 = s[0][3] + s[1][3] + s[2][3] + s[3][3];
        g_ai[n * 2 + 0] = vai0;  g_aj[n * 2 + 0] = vaj0;
        g_ai[n * 2 + 1] = vai1;  g_aj[n * 2 + 1] = vaj1;
        g_amax[n * 2 + 0] = -FLT_MAX;
        g_amax[n * 2 + 1] = -FLT_MAX;
        g_den[n * 2 + 0] = 0.0f;
        g_den[n * 2 + 1] = 0.0f;
    }
}

// ---------------- 3) edge pass 1: e transform, e_out, raw alpha, seg-max --
__global__ void edge_phase1(const float* __restrict__ ein0,
                            const int* __restrict__ src,
                            const int* __restrict__ dst,
                            const float* __restrict__ linE,
                            const float* __restrict__ att,
                            int layer) {
    const int e = blockIdx.x * blockDim.x + threadIdx.x;
    if (e >= N_EDGES) return;

    const float* ein = (layer == 0) ? ein0 : g_ebuf;
    float ea0 = ein[(size_t)e * 4 + 0];
    float ea1 = ein[(size_t)e * 4 + 1];
    float ea2 = ein[(size_t)e * 4 + 2];
    float ea3 = ein[(size_t)e * 4 + 3];

    float eh[8];
#pragma unroll
    for (int c = 0; c < 8; c++)
        eh[c] = fmaf(ea0, linE[c],
                fmaf(ea1, linE[8 + c],
                fmaf(ea2, linE[16 + c], ea3 * linE[24 + c])));

    // e_out = relu(mean over heads) -> feeds next layer
#pragma unroll
    for (int a = 0; a < 4; a++)
        g_ebuf[(size_t)e * 4 + a] = fmaxf(0.5f * (eh[a] + eh[4 + a]), 0.0f);

    int s = src[e], t = dst[e];
#pragma unroll
    for (int h = 0; h < 2; h++) {
        const float* ah = att + h * 260 + 256;
        float ae = fmaf(eh[h * 4 + 0], ah[0],
                   fmaf(eh[h * 4 + 1], ah[1],
                   fmaf(eh[h * 4 + 2], ah[2], eh[h * 4 + 3] * ah[3])));
        float al = g_ai[s * 2 + h] + g_aj[t * 2 + h] + ae;
        al = (al > 0.0f) ? al : NEG * al;          // leaky_relu 0.2
        g_alpha[(size_t)e * 2 + h] = al;
        atomicMaxFloat(&g_amax[t * 2 + h], al);
    }
}

// ---------------- 4) edge pass 2: exp + segment-sum -----------------------
__global__ void edge_phase2(const int* __restrict__ dst) {
    const int e = blockIdx.x * blockDim.x + threadIdx.x;
    if (e >= N_EDGES) return;
    int t = dst[e];
#pragma unroll
    for (int h = 0; h < 2; h++) {
        float ex = __expf(g_alpha[(size_t)e * 2 + h] - g_amax[t * 2 + h]);
        g_alpha[(size_t)e * 2 + h] = ex;
        atomicAdd(&g_den[t * 2 + h], ex);
    }
}

// ---------------- 5) message scatter (head-mean fused) --------------------
// one warp per edge; 8 edges / 256-thread block
__global__ void edge_scatter(const int* __restrict__ src,
                             const int* __restrict__ dst) {
    const int gw = (blockIdx.x * blockDim.x + threadIdx.x) >> 5;
    const int lane = threadIdx.x & 31;
    if (gw >= N_EDGES) return;
    const int e = gw;
    int s = src[e], t = dst[e];
    float w0 = g_alpha[(size_t)e * 2 + 0] / g_den[t * 2 + 0];
    float w1 = g_alpha[(size_t)e * 2 + 1] / g_den[t * 2 + 1];
    const float* xs = &g_xh[(size_t)s * 256];
    float* ap = &g_acc[(size_t)t * DD];
#pragma unroll
    for (int i = 0; i < 4; i++) {
        int d = lane + i * 32;
        float v = 0.5f * fmaf(w0, xs[d], w1 * xs[128 + d]);
        atomicAdd(&ap[d], v);
    }
}

// ---------------- 6) pooling ----------------------------------------------
__global__ void pool_init(float* __restrict__ y, const float* __restrict__ fb) {
    y[threadIdx.x] = fb[0];
}

__global__ void pool_nodes(const int* __restrict__ batch,
                           const float* __restrict__ fw,
                           float* __restrict__ y) {
    const int gw = (blockIdx.x * blockDim.x + threadIdx.x) >> 5;
    const int lane = threadIdx.x & 31;
    if (gw >= N_NODES) return;
    const int n = gw;
    float sum = 0.0f;
#pragma unroll
    for (int i = 0; i < 4; i++) {
        int d = lane + i * 32;
        sum = fmaf(fmaxf(g_acc[(size_t)n * DD + d], 0.0f), fw[d], sum);
    }
#pragma unroll
    for (int o = 16; o > 0; o >>= 1)
        sum += __shfl_down_sync(0xFFFFFFFFu, sum, o);
    if (lane == 0) atomicAdd(&y[batch[n]], sum);
}

// ---------------- launcher ----------------
extern "C" void kernel_launch(void* const* d_in, const int* in_sizes, int n_in,
                              void* d_out, int out_size) {
    const float* x     = (const float*)d_in[0];
    const int*   eidx  = (const int*)  d_in[1];
    const float* eattr = (const float*)d_in[2];
    const int*   batch = (const int*)  d_in[3];
    const float* linN[3] = {(const float*)d_in[4],  (const float*)d_in[8],  (const float*)d_in[12]};
    const float* linE[3] = {(const float*)d_in[5],  (const float*)d_in[9],  (const float*)d_in[13]};
    const float* att[3]  = {(const float*)d_in[6],  (const float*)d_in[10], (const float*)d_in[14]};
    const float* bias[3] = {(const float*)d_in[7],  (const float*)d_in[11], (const float*)d_in[15]};
    const float* fw = (const float*)d_in[16];
    const float* fb = (const float*)d_in[17];
    float* y = (float*)d_out;

    const int* src = eidx;             // edge_index row 0
    const int* dst = eidx + N_EDGES;   // edge_index row 1

    for (int l = 0; l < 3; l++) {
        gemm_node<<<N_NODES / 16, 128>>>(x, linN[l], bias[l], l);
        node_prep<<<N_NODES, 128>>>(att[l]);
        edge_phase1<<<N_EDGES / 256, 256>>>(eattr, src, dst, linE[l], att[l], l);
        edge_phase2<<<N_EDGES / 256, 256>>>(dst);
        edge_scatter<<<N_EDGES / 8, 256>>>(src, dst);
    }
    pool_init<<<1, GG>>>(y, fb);
    pool_nodes<<<N_NODES / 8, 256>>>(batch, fw, y);
}

// round 17
// speedup vs baseline: 1.0016x; 1.0016x over previous
#include <cuda_runtime.h>
#include <math.h>
#include <float.h>

#define N_NODES 50000
#define N_EDGES 800000
#define DD      128
#define AA      4
#define HH      2
#define GG      128
#define NEG     0.2f

// ---------------- device scratch (static, no allocations) ----------------
__device__ float g_xh[N_NODES * HH * DD];    // per-head node features [N,2,128] (51.2MB)
__device__ float g_acc[N_NODES * DD];        // head-mean accumulator / layer output (25.6MB)
__device__ float g_ebuf[N_EDGES * AA];       // edge features between layers (12.8MB)
__device__ float g_alpha[N_EDGES * HH];      // raw alpha, then exp(alpha-max) (6.4MB)
__device__ float g_ai[N_NODES * HH];
__device__ float g_aj[N_NODES * HH];
__device__ float g_amax[N_NODES * HH];
__device__ float g_den[N_NODES * HH];

// ---------------- helpers ----------------
__device__ __forceinline__ void atomicMaxFloat(float* addr, float value) {
    // works across mixed signs: int ordering matches float for >=0,
    // reversed-unsigned ordering matches for <0; atomics serialize.
    if (value >= 0.0f)
        atomicMax((int*)addr, __float_as_int(value));
    else
        atomicMin((unsigned int*)addr, __float_as_uint(value));
}

// ---------------- 1) node GEMM: xh = in @ linN + bias --------------------
// block = 128 threads, computes 16 rows x 256 cols (2 cols/thread).
// layer==0 reads xin; otherwise reads relu(g_acc).
__global__ void gemm_node(const float* __restrict__ xin,
                          const float* __restrict__ W,
                          const float* __restrict__ bias,
                          int layer) {
    __shared__ float sIn[16][DD];
    const int row0 = blockIdx.x * 16;
    const int t = threadIdx.x;

    const float* in = (layer == 0) ? xin : g_acc;
    for (int i = t; i < 16 * DD; i += 128) {
        int m = i >> 7, k = i & 127;
        float v = in[(size_t)(row0 + m) * DD + k];
        if (layer != 0) v = fmaxf(v, 0.0f);
        sIn[m][k] = v;
    }
    __syncthreads();

    float acc0[16], acc1[16];
#pragma unroll
    for (int m = 0; m < 16; m++) { acc0[m] = 0.0f; acc1[m] = 0.0f; }

    const int c0 = 2 * t;
#pragma unroll 4
    for (int k = 0; k < DD; k++) {
        float2 w = *reinterpret_cast<const float2*>(&W[k * 256 + c0]);
#pragma unroll
        for (int m = 0; m < 16; m++) {
            float xv = sIn[m][k];
            acc0[m] = fmaf(xv, w.x, acc0[m]);
            acc1[m] = fmaf(xv, w.y, acc1[m]);
        }
    }

    float b0 = bias[c0], b1 = bias[c0 + 1];
#pragma unroll
    for (int m = 0; m < 16; m++) {
        size_t o = (size_t)(row0 + m) * 256 + c0;
        g_xh[o]     = acc0[m] + b0;
        g_xh[o + 1] = acc1[m] + b1;
    }
}

// ---------------- 2) per-node prep: ai/aj dots, acc init, amax/den init ---
// one block (128 threads) per node
__global__ void node_prep(const float* __restrict__ att) {
    const int n = blockIdx.x;
    const int d = threadIdx.x;

    float x0 = g_xh[(size_t)n * 256 + d];
    float x1 = g_xh[(size_t)n * 256 + 128 + d];
    g_acc[(size_t)n * DD + d] = 0.5f * (x0 + x1);

    float ai0 = x0 * att[d];
    float aj0 = x0 * att[128 + d];
    float ai1 = x1 * att[260 + d];
    float aj1 = x1 * att[260 + 128 + d];

#pragma unroll
    for (int o = 16; o > 0; o >>= 1) {
        ai0 += __shfl_down_sync(0xFFFFFFFFu, ai0, o);
        aj0 += __shfl_down_sync(0xFFFFFFFFu, aj0, o);
        ai1 += __shfl_down_sync(0xFFFFFFFFu, ai1, o);
        aj1 += __shfl_down_sync(0xFFFFFFFFu, aj1, o);
    }
    __shared__ float s[4][4];
    int w = d >> 5, l = d & 31;
    if (l == 0) { s[w][0] = ai0; s[w][1] = aj0; s[w][2] = ai1; s[w][3] = aj1; }
    __syncthreads();
    if (d == 0) {
        float vai0 = s[0][0] + s[1][0] + s[2][0] + s[3][0];
        float vaj0 = s[0][1] + s[1][1] + s[2][1] + s[3][1];
        float vai1 = s[0][2] + s[1][2] + s[2][2] + s[3][2];
        float vaj1 = s[0][3] + s[1][3] + s[2][3] + s[3][3];
        g_ai[n * 2 + 0] = vai0;  g_aj[n * 2 + 0] = vaj0;
        g_ai[n * 2 + 1] = vai1;  g_aj[n * 2 + 1] = vaj1;
        g_amax[n * 2 + 0] = -FLT_MAX;
        g_amax[n * 2 + 1] = -FLT_MAX;
        g_den[n * 2 + 0] = 0.0f;
        g_den[n * 2 + 1] = 0.0f;
    }
}

// ---------------- 3) edge pass 1: e transform, e_out, raw alpha, seg-max --
__global__ void edge_phase1(const float* __restrict__ ein0,
                            const int* __restrict__ src,
                            const int* __restrict__ dst,
                            const float* __restrict__ linE,
                            const float* __restrict__ att,
                            int layer) {
    const int e = blockIdx.x * blockDim.x + threadIdx.x;
    if (e >= N_EDGES) return;

    const float* ein = (layer == 0) ? ein0 : g_ebuf;
    float ea0 = ein[(size_t)e * 4 + 0];
    float ea1 = ein[(size_t)e * 4 + 1];
    float ea2 = ein[(size_t)e * 4 + 2];
    float ea3 = ein[(size_t)e * 4 + 3];

    float eh[8];
#pragma unroll
    for (int c = 0; c < 8; c++)
        eh[c] = fmaf(ea0, linE[c],
                fmaf(ea1, linE[8 + c],
                fmaf(ea2, linE[16 + c], ea3 * linE[24 + c])));

    // e_out = relu(mean over heads) -> feeds next layer
#pragma unroll
    for (int a = 0; a < 4; a++)
        g_ebuf[(size_t)e * 4 + a] = fmaxf(0.5f * (eh[a] + eh[4 + a]), 0.0f);

    int s = src[e], t = dst[e];
#pragma unroll
    for (int h = 0; h < 2; h++) {
        const float* ah = att + h * 260 + 256;
        float ae = fmaf(eh[h * 4 + 0], ah[0],
                   fmaf(eh[h * 4 + 1], ah[1],
                   fmaf(eh[h * 4 + 2], ah[2], eh[h * 4 + 3] * ah[3])));
        float al = g_ai[s * 2 + h] + g_aj[t * 2 + h] + ae;
        al = (al > 0.0f) ? al : NEG * al;          // leaky_relu 0.2
        g_alpha[(size_t)e * 2 + h] = al;
        atomicMaxFloat(&g_amax[t * 2 + h], al);
    }
}

// ---------------- 4) edge pass 2: exp + segment-sum -----------------------
__global__ void edge_phase2(const int* __restrict__ dst) {
    const int e = blockIdx.x * blockDim.x + threadIdx.x;
    if (e >= N_EDGES) return;
    int t = dst[e];
#pragma unroll
    for (int h = 0; h < 2; h++) {
        float ex = __expf(g_alpha[(size_t)e * 2 + h] - g_amax[t * 2 + h]);
        g_alpha[(size_t)e * 2 + h] = ex;
        atomicAdd(&g_den[t * 2 + h], ex);
    }
}

// ---------------- 5) message scatter (head-mean fused) --------------------
// one warp per edge; 8 edges / 256-thread block
__global__ void edge_scatter(const int* __restrict__ src,
                             const int* __restrict__ dst) {
    const int gw = (blockIdx.x * blockDim.x + threadIdx.x) >> 5;
    const int lane = threadIdx.x & 31;
    if (gw >= N_EDGES) return;
    const int e = gw;
    int s = src[e], t = dst[e];
    float w0 = g_alpha[(size_t)e * 2 + 0] / g_den[t * 2 + 0];
    float w1 = g_alpha[(size_t)e * 2 + 1] / g_den[t * 2 + 1];
    const float* xs = &g_xh[(size_t)s * 256];
    float* ap = &g_acc[(size_t)t * DD];
#pragma unroll
    for (int i = 0; i < 4; i++) {
        int d = lane + i * 32;
        float v = 0.5f * fmaf(w0, xs[d], w1 * xs[128 + d]);
        atomicAdd(&ap[d], v);
    }
}

// ---------------- 6) pooling ----------------------------------------------
__global__ void pool_init(float* __restrict__ y, const float* __restrict__ fb) {
    y[threadIdx.x] = fb[0];
}

__global__ void pool_nodes(const int* __restrict__ batch,
                           const float* __restrict__ fw,
                           float* __restrict__ y) {
    const int gw = (blockIdx.x * blockDim.x + threadIdx.x) >> 5;
    const int lane = threadIdx.x & 31;
    if (gw >= N_NODES) return;
    const int n = gw;
    float sum = 0.0f;
#pragma unroll
    for (int i = 0; i < 4; i++) {
        int d = lane + i * 32;
        sum = fmaf(fmaxf(g_acc[(size_t)n * DD + d], 0.0f), fw[d], sum);
    }
#pragma unroll
    for (int o = 16; o > 0; o >>= 1)
        sum += __shfl_down_sync(0xFFFFFFFFu, sum, o);
    if (lane == 0) atomicAdd(&y[batch[n]], sum);
}

// ---------------- launcher ----------------
extern "C" void kernel_launch(void* const* d_in, const int* in_sizes, int n_in,
                              void* d_out, int out_size) {
    const float* x     = (const float*)d_in[0];
    const int*   eidx  = (const int*)  d_in[1];
    const float* eattr = (const float*)d_in[2];
    const int*   batch = (const int*)  d_in[3];
    const float* linN[3] = {(const float*)d_in[4],  (const float*)d_in[8],  (const float*)d_in[12]};
    const float* linE[3] = {(const float*)d_in[5],  (const float*)d_in[9],  (const float*)d_in[13]};
    const float* att[3]  = {(const float*)d_in[6],  (const float*)d_in[10], (const float*)d_in[14]};
    const float* bias[3] = {(const float*)d_in[7],  (const float*)d_in[11], (const float*)d_in[15]};
    const float* fw = (const float*)d_in[16];
    const float* fb = (const float*)d_in[17];
    float* y = (float*)d_out;

    const int* src = eidx;             // edge_index row 0
    const int* dst = eidx + N_EDGES;   // edge_index row 1

    for (int l = 0; l < 3; l++) {
        gemm_node<<<N_NODES / 16, 128>>>(x, linN[l], bias[l], l);
        node_prep<<<N_NODES, 128>>>(att[l]);
        edge_phase1<<<N_EDGES / 256, 256>>>(eattr, src, dst, linE[l], att[l], l);
        edge_phase2<<<N_EDGES / 256, 256>>>(dst);
        edge_scatter<<<N_EDGES / 8, 256>>>(src, dst);
    }
    pool_init<<<1, GG>>>(y, fb);
    pool_nodes<<<N_NODES / 8, 256>>>(batch, fw, y);
}